// round 2
// baseline (speedup 1.0000x reference)
#include <cuda_runtime.h>

#define N_NODES 100000
#define DIMS    128
#define N_EDGES 1600000

// Scratch (allocation-free rule: __device__ globals)
__device__ float g_agg[(size_t)N_NODES * DIMS];   // 51.2 MB aggregated raw-x
__device__ float g_w1t[DIMS * DIMS];              // W1 transposed: [k][j]
__device__ float g_w2t[DIMS * DIMS];              // W2 transposed: [k][j]

// ---------------------------------------------------------------------------
// Zero the aggregation buffer (float4 stores)
// ---------------------------------------------------------------------------
__global__ void k_zero_agg() {
    size_t i = (size_t)blockIdx.x * blockDim.x + threadIdx.x;
    if (i < (size_t)N_NODES * (DIMS / 4)) {
        reinterpret_cast<float4*>(g_agg)[i] = make_float4(0.f, 0.f, 0.f, 0.f);
    }
}

// ---------------------------------------------------------------------------
// Transpose W1, W2 (128x128, [j][k] -> [k][j]) once per launch
// ---------------------------------------------------------------------------
__global__ void k_transpose_w(const float* __restrict__ W1,
                              const float* __restrict__ W2) {
    int i = blockIdx.x * 256 + threadIdx.x;
    if (i < DIMS * DIMS) {
        int j = i >> 7;      // output row
        int k = i & 127;     // input dim
        g_w1t[k * DIMS + j] = W1[i];
        g_w2t[k * DIMS + j] = W2[i];
    }
}

// ---------------------------------------------------------------------------
// Scatter: for each edge e, g_agg[row[e]] += x[col[e]]
// One warp per edge; lane l carries float4 l (32*16B = 128 floats = 1 row).
// atomicAdd(float4*) -> RED.E.128 (cc >= 9.0), no return value used.
// Edge index is int32 (JAX default x64-disabled downcasts jnp.int64).
// Bound-guard: if dtype theory is wrong we get rel_err, not a crash.
// ---------------------------------------------------------------------------
__global__ void k_scatter(const float* __restrict__ x,
                          const int* __restrict__ ei,
                          int E, int N) {
    int w = (int)((blockIdx.x * (size_t)blockDim.x + threadIdx.x) >> 5);
    if (w >= E) return;
    int lane = threadIdx.x & 31;
    int row = ei[w];        // destination (scatter index)
    int col = ei[E + w];    // source (gather index)
    if ((unsigned)row >= (unsigned)N || (unsigned)col >= (unsigned)N) return;

    const float4* xs = reinterpret_cast<const float4*>(x) + (size_t)col * 32;
    float4 v = xs[lane];
    atomicAdd(reinterpret_cast<float4*>(g_agg) + (size_t)row * 32 + lane, v);
}

// ---------------------------------------------------------------------------
// Fused dual GEMM + relu epilogue:
//   out[i][j] = relu( sum_k x[i][k]*W1[j][k] + sum_k agg[i][k]*W2[j][k] )
// Block tile: 64 rows x 128 cols. 256 threads, micro-tile 4x8.
// Smem: x tile 32KB + agg tile 32KB + W1T 64KB + W2T 64KB = 192KB dynamic.
// ---------------------------------------------------------------------------
#define BM 64
#define TM 4
#define TN 8

__global__ void __launch_bounds__(256, 1)
k_fused_gemm(const float* __restrict__ x,
             float* __restrict__ out,
             int N) {
    extern __shared__ float smem[];
    float* sx  = smem;               // [64][128]
    float* sa  = smem + BM * DIMS;   // [64][128]
    float* sw1 = sa   + BM * DIMS;   // [128][128] (k-major: [k][j])
    float* sw2 = sw1  + DIMS * DIMS; // [128][128]

    int tid = threadIdx.x;
    int tx = tid & 15;    // col group: cols tx*8 .. tx*8+7
    int ty = tid >> 4;    // row group: rows ty*4 .. ty*4+3
    int row0 = blockIdx.x * BM;

    // --- Fill smem (all coalesced float4) ---
    const float4* xg = reinterpret_cast<const float4*>(x);
    const float4* ag = reinterpret_cast<const float4*>(g_agg);
    float4* sx4 = reinterpret_cast<float4*>(sx);
    float4* sa4 = reinterpret_cast<float4*>(sa);
    #pragma unroll
    for (int i = tid; i < BM * (DIMS / 4); i += 256) {
        int r = i >> 5;           // local row
        int gr = row0 + r;
        float4 xv = make_float4(0.f, 0.f, 0.f, 0.f);
        float4 av = make_float4(0.f, 0.f, 0.f, 0.f);
        if (gr < N) {
            size_t base = (size_t)gr * 32 + (i & 31);
            xv = xg[base];
            av = ag[base];
        }
        sx4[i] = xv;
        sa4[i] = av;
    }
    const float4* w1g = reinterpret_cast<const float4*>(g_w1t);
    const float4* w2g = reinterpret_cast<const float4*>(g_w2t);
    float4* sw14 = reinterpret_cast<float4*>(sw1);
    float4* sw24 = reinterpret_cast<float4*>(sw2);
    #pragma unroll
    for (int i = tid; i < DIMS * (DIMS / 4); i += 256) {
        sw14[i] = w1g[i];
        sw24[i] = w2g[i];
    }
    __syncthreads();

    float acc[TM][TN];
    #pragma unroll
    for (int r = 0; r < TM; r++)
        #pragma unroll
        for (int c = 0; c < TN; c++)
            acc[r][c] = 0.f;

    const float4* sxr4 = reinterpret_cast<const float4*>(sx);
    const float4* sar4 = reinterpret_cast<const float4*>(sa);

    // main loop over k in chunks of 4
    #pragma unroll 4
    for (int k4 = 0; k4 < DIMS / 4; k4++) {
        float xq[TM][4], aq[TM][4];
        #pragma unroll
        for (int r = 0; r < TM; r++) {
            float4 t = sxr4[(ty * TM + r) * 32 + k4];
            xq[r][0] = t.x; xq[r][1] = t.y; xq[r][2] = t.z; xq[r][3] = t.w;
            float4 u = sar4[(ty * TM + r) * 32 + k4];
            aq[r][0] = u.x; aq[r][1] = u.y; aq[r][2] = u.z; aq[r][3] = u.w;
        }
        #pragma unroll
        for (int kk = 0; kk < 4; kk++) {
            int k = k4 * 4 + kk;
            float4 wa = sw14[k * 32 + (tx << 1)];
            float4 wb = sw14[k * 32 + (tx << 1) + 1];
            float4 va = sw24[k * 32 + (tx << 1)];
            float4 vb = sw24[k * 32 + (tx << 1) + 1];
            float w1v[TN] = {wa.x, wa.y, wa.z, wa.w, wb.x, wb.y, wb.z, wb.w};
            float w2v[TN] = {va.x, va.y, va.z, va.w, vb.x, vb.y, vb.z, vb.w};
            #pragma unroll
            for (int r = 0; r < TM; r++) {
                float xr = xq[r][kk];
                float ar = aq[r][kk];
                #pragma unroll
                for (int c = 0; c < TN; c++) {
                    acc[r][c] = fmaf(xr, w1v[c], acc[r][c]);
                    acc[r][c] = fmaf(ar, w2v[c], acc[r][c]);
                }
            }
        }
    }

    // epilogue: relu + store (float4)
    float4* og = reinterpret_cast<float4*>(out);
    #pragma unroll
    for (int r = 0; r < TM; r++) {
        int gr = row0 + ty * TM + r;
        if (gr < N) {
            float4 o1, o2;
            o1.x = fmaxf(acc[r][0], 0.f); o1.y = fmaxf(acc[r][1], 0.f);
            o1.z = fmaxf(acc[r][2], 0.f); o1.w = fmaxf(acc[r][3], 0.f);
            o2.x = fmaxf(acc[r][4], 0.f); o2.y = fmaxf(acc[r][5], 0.f);
            o2.z = fmaxf(acc[r][6], 0.f); o2.w = fmaxf(acc[r][7], 0.f);
            size_t base = (size_t)gr * 32 + (tx << 1);
            og[base]     = o1;
            og[base + 1] = o2;
        }
    }
}

// ---------------------------------------------------------------------------
// Launch
// ---------------------------------------------------------------------------
extern "C" void kernel_launch(void* const* d_in, const int* in_sizes, int n_in,
                              void* d_out, int out_size) {
    const float* x  = (const float*)d_in[0];
    const int*   ei = (const int*)d_in[1];
    const float* W1 = (const float*)d_in[2];
    const float* W2 = (const float*)d_in[3];
    float* out = (float*)d_out;

    int N = in_sizes[0] / DIMS;       // 100000
    int E = in_sizes[1] / 2;          // 1600000

    // zero agg
    {
        int total = N * (DIMS / 4);
        k_zero_agg<<<(total + 255) / 256, 256>>>();
    }
    // transpose weights
    k_transpose_w<<<(DIMS * DIMS + 255) / 256, 256>>>(W1, W2);

    // scatter raw x into agg
    {
        size_t threads = (size_t)E * 32;
        int blocks = (int)((threads + 255) / 256);
        k_scatter<<<blocks, 256>>>(x, ei, E, N);
    }

    // fused dual-GEMM + relu
    {
        int smem_bytes = (2 * BM * DIMS + 2 * DIMS * DIMS) * sizeof(float); // 192KB
        cudaFuncSetAttribute(k_fused_gemm,
                             cudaFuncAttributeMaxDynamicSharedMemorySize,
                             smem_bytes);
        int blocks = (N + BM - 1) / BM;
        k_fused_gemm<<<blocks, 256, smem_bytes>>>(x, out, N);
    }
}

// round 3
// speedup vs baseline: 1.4371x; 1.4371x over previous
#include <cuda_runtime.h>

#define N_NODES 100000
#define DIMS    128

// Scratch (allocation-free rule: __device__ globals)
__device__ float g_agg[(size_t)N_NODES * DIMS];   // 51.2 MB aggregated raw-x

// ---------------------------------------------------------------------------
// Zero the aggregation buffer (float4 stores)
// ---------------------------------------------------------------------------
__global__ void k_zero_agg() {
    size_t i = (size_t)blockIdx.x * blockDim.x + threadIdx.x;
    if (i < (size_t)N_NODES * (DIMS / 4)) {
        reinterpret_cast<float4*>(g_agg)[i] = make_float4(0.f, 0.f, 0.f, 0.f);
    }
}

// ---------------------------------------------------------------------------
// Scatter: for each edge e, g_agg[row[e]] += x[col[e]]
// One warp per edge; lane l carries float4 l. RED.E.128, L2-BW bound.
// ---------------------------------------------------------------------------
__global__ void k_scatter(const float* __restrict__ x,
                          const int* __restrict__ ei,
                          int E, int N) {
    int w = (int)((blockIdx.x * (size_t)blockDim.x + threadIdx.x) >> 5);
    if (w >= E) return;
    int lane = threadIdx.x & 31;
    int row = ei[w];        // destination (scatter index)
    int col = ei[E + w];    // source (gather index)
    if ((unsigned)row >= (unsigned)N || (unsigned)col >= (unsigned)N) return;

    const float4* xs = reinterpret_cast<const float4*>(x) + (size_t)col * 32;
    float4 v = xs[lane];
    atomicAdd(reinterpret_cast<float4*>(g_agg) + (size_t)row * 32 + lane, v);
}

// ---------------------------------------------------------------------------
// TF32 tensor-core GEMM:
//   out = relu( [x | agg] (M x 256) @ [W1 | W2]^T (256 x 128) )
// CTA tile 128x128, 8 warps (each 32 rows x 64 cols), mma.m16n8k8.tf32.
// Weights staged once per CTA; A double-buffered in 32-k chunks.
// Smem k-layout is pair-permuted: group of 8 k stored as
//   [k0, k0+4, k0+1, k0+5, k0+2, k0+6, k0+3, k0+7]
// so a thread's (frag, frag+4k) pair is one float2 (LDS.64), conflict-free
// with strides chosen below.
// ---------------------------------------------------------------------------
#define STRIDE_W 264                      // floats per n-row of W (256 k + 8 pad)
#define STRIDE_A 40                       // floats per m-row of A chunk (32 k + 8 pad)
#define SMEM_W_FLOATS (128 * STRIDE_W)    // 33792
#define SMEM_A_FLOATS (128 * STRIDE_A)    // 5120 per buffer

__device__ __forceinline__ float to_tf32(float f) {
    unsigned u;
    asm("cvt.rna.tf32.f32 %0, %1;" : "=r"(u) : "f"(f));
    return __uint_as_float(u);
}

__device__ __forceinline__ void mma_tf32(float d[4],
                                         const unsigned a[4],
                                         unsigned b0, unsigned b1) {
    asm volatile(
        "mma.sync.aligned.m16n8k8.row.col.f32.tf32.tf32.f32 "
        "{%0,%1,%2,%3},{%4,%5,%6,%7},{%8,%9},{%0,%1,%2,%3};"
        : "+f"(d[0]), "+f"(d[1]), "+f"(d[2]), "+f"(d[3])
        : "r"(a[0]), "r"(a[1]), "r"(a[2]), "r"(a[3]), "r"(b0), "r"(b1));
}

__global__ void __launch_bounds__(256, 1)
k_mma_gemm(const float* __restrict__ x,
           const float* __restrict__ W1,
           const float* __restrict__ W2,
           float* __restrict__ out, int N)
{
    extern __shared__ float sm[];
    float* sW  = sm;                         // [128][264]
    float* sA0 = sm + SMEM_W_FLOATS;         // [128][40]
    float* sA1 = sA0 + SMEM_A_FLOATS;

    const int tid   = threadIdx.x;
    const int lane  = tid & 31;
    const int wid   = tid >> 5;
    const int gid   = lane >> 2;   // 0..7
    const int tig   = lane & 3;    // 0..3
    const int warp_m = wid & 3;    // 0..3  -> rows 32*warp_m
    const int warp_n = wid >> 2;   // 0..1  -> cols 64*warp_n
    const int row0  = blockIdx.x * 128;

    // ---- Stage weights once (tf32, pair-permuted). 4096 groups of 8 k. ----
    {
        const float4* W1_4 = reinterpret_cast<const float4*>(W1);
        const float4* W2_4 = reinterpret_cast<const float4*>(W2);
        #pragma unroll 4
        for (int g = tid; g < 4096; g += 256) {
            int mtx = g >> 11;             // 0 = W1 (k 0..127), 1 = W2 (k 128..255)
            int n   = (g >> 4) & 127;
            int k8  = g & 15;              // group-of-8 within the 128-k half
            const float4* src = mtx ? W2_4 : W1_4;
            float4 lo = src[n * 32 + k8 * 2];
            float4 hi = src[n * 32 + k8 * 2 + 1];
            float* dst = sW + n * STRIDE_W + mtx * 128 + k8 * 8;
            float4 s0 = make_float4(to_tf32(lo.x), to_tf32(hi.x),
                                    to_tf32(lo.y), to_tf32(hi.y));
            float4 s1 = make_float4(to_tf32(lo.z), to_tf32(hi.z),
                                    to_tf32(lo.w), to_tf32(hi.w));
            reinterpret_cast<float4*>(dst)[0] = s0;
            reinterpret_cast<float4*>(dst)[1] = s1;
        }
    }

    // ---- Stage A chunk 0 (x columns 0..31) ----
    {
        #pragma unroll
        for (int i = 0; i < 2; i++) {
            int g  = tid + i * 256;        // 512 groups: 128 rows x 4 k-groups
            int r  = g >> 2;
            int k8 = g & 3;
            int gr = row0 + r;
            float4 lo = make_float4(0.f, 0.f, 0.f, 0.f);
            float4 hi = lo;
            if (gr < N) {
                const float4* src = reinterpret_cast<const float4*>(x);
                lo = src[(size_t)gr * 32 + k8 * 2];
                hi = src[(size_t)gr * 32 + k8 * 2 + 1];
            }
            float* dst = sA0 + r * STRIDE_A + k8 * 8;
            reinterpret_cast<float4*>(dst)[0] =
                make_float4(to_tf32(lo.x), to_tf32(hi.x), to_tf32(lo.y), to_tf32(hi.y));
            reinterpret_cast<float4*>(dst)[1] =
                make_float4(to_tf32(lo.z), to_tf32(hi.z), to_tf32(lo.w), to_tf32(hi.w));
        }
    }
    __syncthreads();

    float d[2][8][4];
    #pragma unroll
    for (int m = 0; m < 2; m++)
        #pragma unroll
        for (int j = 0; j < 8; j++)
            #pragma unroll
            for (int q = 0; q < 4; q++)
                d[m][j][q] = 0.f;

    float* bufs[2] = { sA0, sA1 };

    for (int c = 0; c < 8; c++) {
        // Prefetch chunk c+1 into registers (global loads only; overlap w/ mma)
        float4 plo[2], phi[2];
        if (c < 7) {
            int cn = c + 1;
            const float4* src = reinterpret_cast<const float4*>(cn < 4 ? x : g_agg);
            #pragma unroll
            for (int i = 0; i < 2; i++) {
                int g  = tid + i * 256;
                int r  = g >> 2;
                int k8 = g & 3;
                int gr = row0 + r;
                plo[i] = make_float4(0.f, 0.f, 0.f, 0.f);
                phi[i] = plo[i];
                if (gr < N) {
                    size_t base = (size_t)gr * 32 + (cn & 3) * 8 + k8 * 2;
                    plo[i] = src[base];
                    phi[i] = src[base + 1];
                }
            }
        }

        // Compute on buffer c&1; chunk c covers global k in [c*32, c*32+32)
        const float* bufA = bufs[c & 1];
        const int kglob0 = c * 32;
        #pragma unroll
        for (int kk = 0; kk < 4; kk++) {
            int k0 = kk * 8;
            // A fragments (2 m-frags), each one LDS.64 pair per 16-row half
            unsigned a[2][4];
            #pragma unroll
            for (int m = 0; m < 2; m++) {
                int row = warp_m * 32 + m * 16 + gid;
                float2 v0 = reinterpret_cast<const float2*>(bufA + row * STRIDE_A + k0)[tig];
                float2 v1 = reinterpret_cast<const float2*>(bufA + (row + 8) * STRIDE_A + k0)[tig];
                a[m][0] = __float_as_uint(v0.x);  // (row,   k)
                a[m][1] = __float_as_uint(v1.x);  // (row+8, k)
                a[m][2] = __float_as_uint(v0.y);  // (row,   k+4)
                a[m][3] = __float_as_uint(v1.y);  // (row+8, k+4)
            }
            // B fragments (8 n-frags)
            unsigned b0[8], b1[8];
            #pragma unroll
            for (int j = 0; j < 8; j++) {
                int n = warp_n * 64 + j * 8 + gid;
                float2 w = reinterpret_cast<const float2*>(sW + n * STRIDE_W + kglob0 + k0)[tig];
                b0[j] = __float_as_uint(w.x);
                b1[j] = __float_as_uint(w.y);
            }
            #pragma unroll
            for (int m = 0; m < 2; m++)
                #pragma unroll
                for (int j = 0; j < 8; j++)
                    mma_tf32(d[m][j], a[m], b0[j], b1[j]);
        }

        if (c < 7) {
            __syncthreads();   // everyone done reading bufs[(c+1)&1] (used at c-1)
            float* dstB = bufs[(c + 1) & 1];
            #pragma unroll
            for (int i = 0; i < 2; i++) {
                int g  = tid + i * 256;
                int r  = g >> 2;
                int k8 = g & 3;
                float* dst = dstB + r * STRIDE_A + k8 * 8;
                reinterpret_cast<float4*>(dst)[0] =
                    make_float4(to_tf32(plo[i].x), to_tf32(phi[i].x),
                                to_tf32(plo[i].y), to_tf32(phi[i].y));
                reinterpret_cast<float4*>(dst)[1] =
                    make_float4(to_tf32(plo[i].z), to_tf32(phi[i].z),
                                to_tf32(plo[i].w), to_tf32(phi[i].w));
            }
            __syncthreads();
        }
    }

    // ---- Epilogue: relu + float2 stores ----
    #pragma unroll
    for (int m = 0; m < 2; m++) {
        int r  = row0 + warp_m * 32 + m * 16 + gid;
        #pragma unroll
        for (int j = 0; j < 8; j++) {
            int cbase = warp_n * 64 + j * 8 + tig * 2;
            if (r < N) {
                float2 o = make_float2(fmaxf(d[m][j][0], 0.f), fmaxf(d[m][j][1], 0.f));
                *reinterpret_cast<float2*>(out + (size_t)r * 128 + cbase) = o;
            }
            if (r + 8 < N) {
                float2 o = make_float2(fmaxf(d[m][j][2], 0.f), fmaxf(d[m][j][3], 0.f));
                *reinterpret_cast<float2*>(out + (size_t)(r + 8) * 128 + cbase) = o;
            }
        }
    }
}

// ---------------------------------------------------------------------------
// Launch
// ---------------------------------------------------------------------------
extern "C" void kernel_launch(void* const* d_in, const int* in_sizes, int n_in,
                              void* d_out, int out_size) {
    const float* x  = (const float*)d_in[0];
    const int*   ei = (const int*)d_in[1];
    const float* W1 = (const float*)d_in[2];
    const float* W2 = (const float*)d_in[3];
    float* out = (float*)d_out;

    int N = in_sizes[0] / DIMS;       // 100000
    int E = in_sizes[1] / 2;          // 1600000

    // zero agg
    {
        int total = N * (DIMS / 4);
        k_zero_agg<<<(total + 255) / 256, 256>>>();
    }

    // scatter raw x into agg
    {
        size_t threads = (size_t)E * 32;
        int blocks = (int)((threads + 255) / 256);
        k_scatter<<<blocks, 256>>>(x, ei, E, N);
    }

    // tf32 tensor-core GEMM + relu
    {
        int smem_bytes = (SMEM_W_FLOATS + 2 * SMEM_A_FLOATS) * sizeof(float); // 176128
        cudaFuncSetAttribute(k_mma_gemm,
                             cudaFuncAttributeMaxDynamicSharedMemorySize,
                             smem_bytes);
        int blocks = (N + 127) / 128;
        k_mma_gemm<<<blocks, 256, smem_bytes>>>(x, W1, W2, out, N);
    }
}

// round 4
// speedup vs baseline: 2.2326x; 1.5535x over previous
#include <cuda_runtime.h>

#define NMAX 100000
#define EMAX 1600000
#define DIMS 128

// Scratch (allocation-free rule: __device__ globals)
__device__ float g_agg[(size_t)NMAX * DIMS];   // 51.2 MB aggregated raw-x
__device__ int   g_deg[NMAX];                  // in-degree histogram
__device__ int   g_start[NMAX];                // CSR offsets (exclusive scan)
__device__ int   g_cursor[NMAX];               // fill cursors
__device__ int   g_csr[EMAX];                  // CSR column (source) list
__device__ int   g_bsum[256];                  // block sums for scan

// ---------------------------------------------------------------------------
// CSR build
// ---------------------------------------------------------------------------
__global__ void k_clear_deg(int N) {
    int i = blockIdx.x * blockDim.x + threadIdx.x;
    if (i < N) g_deg[i] = 0;
}

__global__ void k_hist(const int* __restrict__ ei, int E, int N) {
    int e = blockIdx.x * blockDim.x + threadIdx.x;
    if (e >= E) return;
    int row = ei[e];
    if ((unsigned)row < (unsigned)N) atomicAdd(&g_deg[row], 1);
}

// Per-block Hillis-Steele scan of 512 elements
__global__ void k_scan_block(int N) {
    __shared__ int s[512];
    int tid = threadIdx.x;
    int i = blockIdx.x * 512 + tid;
    int v = (i < N) ? g_deg[i] : 0;
    s[tid] = v;
    __syncthreads();
    #pragma unroll
    for (int off = 1; off < 512; off <<= 1) {
        int t = (tid >= off) ? s[tid - off] : 0;
        __syncthreads();
        s[tid] += t;
        __syncthreads();
    }
    if (i < N) g_start[i] = s[tid] - v;              // exclusive, block-local
    if (tid == 511) g_bsum[blockIdx.x] = s[511];     // block total
}

__global__ void k_scan_top(int NB) {   // NB <= 256, single block of 256
    __shared__ int s[256];
    int tid = threadIdx.x;
    int v = (tid < NB) ? g_bsum[tid] : 0;
    s[tid] = v;
    __syncthreads();
    #pragma unroll
    for (int off = 1; off < 256; off <<= 1) {
        int t = (tid >= off) ? s[tid - off] : 0;
        __syncthreads();
        s[tid] += t;
        __syncthreads();
    }
    if (tid < NB) g_bsum[tid] = s[tid] - v;          // exclusive block offsets
}

__global__ void k_scan_add(int N) {
    int i = blockIdx.x * blockDim.x + threadIdx.x;
    if (i >= N) return;
    int st = g_start[i] + g_bsum[i >> 9];
    g_start[i]  = st;
    g_cursor[i] = st;
}

__global__ void k_fill(const int* __restrict__ ei, int E, int N) {
    int e = blockIdx.x * blockDim.x + threadIdx.x;
    if (e >= E) return;
    int row = ei[e];
    int col = ei[E + e];
    if ((unsigned)row >= (unsigned)N || (unsigned)col >= (unsigned)N) return;
    int pos = atomicAdd(&g_cursor[row], 1);
    g_csr[pos] = col;
}

// ---------------------------------------------------------------------------
// Gather-aggregate: one warp per node. agg[n] = sum_{c in csr[n]} x[c]
// Lane l carries float4 l of the 128-float row. Plain loads + one store;
// no atomics, no zero-init needed.
// ---------------------------------------------------------------------------
__global__ void k_aggregate(const float* __restrict__ x, int N) {
    int node = (int)((blockIdx.x * (size_t)blockDim.x + threadIdx.x) >> 5);
    if (node >= N) return;
    int lane = threadIdx.x & 31;
    int start = g_start[node];
    int deg   = g_deg[node];

    const float4* x4 = reinterpret_cast<const float4*>(x);
    float4 acc = make_float4(0.f, 0.f, 0.f, 0.f);

    for (int base = 0; base < deg; base += 32) {
        int nn = deg - base; if (nn > 32) nn = 32;
        int col = (lane < nn) ? g_csr[start + base + lane] : 0;
        for (int j = 0; j < nn; j++) {
            int c = __shfl_sync(0xffffffffu, col, j);
            float4 v = x4[(size_t)c * 32 + lane];
            acc.x += v.x; acc.y += v.y; acc.z += v.z; acc.w += v.w;
        }
    }
    reinterpret_cast<float4*>(g_agg)[(size_t)node * 32 + lane] = acc;
}

// ---------------------------------------------------------------------------
// Persistent TF32 tensor-core GEMM:
//   out = relu( [x | agg] (M x 256) @ [W1 | W2]^T (256 x 128) )
// 148 CTAs; weights staged ONCE per CTA, then loop over 128-row tiles.
// Per tile: A double-buffered in 32-k chunks, mma.m16n8k8.tf32.
// Smem k-layout pair-permuted ([k, k+4] adjacent) -> LDS.64 frag loads.
// ---------------------------------------------------------------------------
#define STRIDE_W 264
#define STRIDE_A 40
#define SMEM_W_FLOATS (128 * STRIDE_W)    // 33792
#define SMEM_A_FLOATS (128 * STRIDE_A)    // 5120 per buffer

__device__ __forceinline__ float to_tf32(float f) {
    unsigned u;
    asm("cvt.rna.tf32.f32 %0, %1;" : "=r"(u) : "f"(f));
    return __uint_as_float(u);
}

__device__ __forceinline__ void mma_tf32(float d[4],
                                         const unsigned a[4],
                                         unsigned b0, unsigned b1) {
    asm volatile(
        "mma.sync.aligned.m16n8k8.row.col.f32.tf32.tf32.f32 "
        "{%0,%1,%2,%3},{%4,%5,%6,%7},{%8,%9},{%0,%1,%2,%3};"
        : "+f"(d[0]), "+f"(d[1]), "+f"(d[2]), "+f"(d[3])
        : "r"(a[0]), "r"(a[1]), "r"(a[2]), "r"(a[3]), "r"(b0), "r"(b1));
}

__global__ void __launch_bounds__(256, 1)
k_mma_gemm(const float* __restrict__ x,
           const float* __restrict__ W1,
           const float* __restrict__ W2,
           float* __restrict__ out, int N)
{
    extern __shared__ float sm[];
    float* sW  = sm;                         // [128][264]
    float* sA0 = sm + SMEM_W_FLOATS;         // [128][40]
    float* sA1 = sA0 + SMEM_A_FLOATS;

    const int tid    = threadIdx.x;
    const int lane   = tid & 31;
    const int wid    = tid >> 5;
    const int gid    = lane >> 2;   // 0..7
    const int tig    = lane & 3;    // 0..3
    const int warp_m = wid & 3;     // rows 32*warp_m
    const int warp_n = wid >> 2;    // cols 64*warp_n

    // ---- Stage weights ONCE (tf32, pair-permuted). ----
    {
        const float4* W1_4 = reinterpret_cast<const float4*>(W1);
        const float4* W2_4 = reinterpret_cast<const float4*>(W2);
        #pragma unroll 4
        for (int g = tid; g < 4096; g += 256) {
            int mtx = g >> 11;
            int n   = (g >> 4) & 127;
            int k8  = g & 15;
            const float4* src = mtx ? W2_4 : W1_4;
            float4 lo = src[n * 32 + k8 * 2];
            float4 hi = src[n * 32 + k8 * 2 + 1];
            float* dst = sW + n * STRIDE_W + mtx * 128 + k8 * 8;
            reinterpret_cast<float4*>(dst)[0] =
                make_float4(to_tf32(lo.x), to_tf32(hi.x), to_tf32(lo.y), to_tf32(hi.y));
            reinterpret_cast<float4*>(dst)[1] =
                make_float4(to_tf32(lo.z), to_tf32(hi.z), to_tf32(lo.w), to_tf32(hi.w));
        }
    }

    float* bufs[2] = { sA0, sA1 };
    const int ntiles = (N + 127) / 128;

    for (int tile = blockIdx.x; tile < ntiles; tile += gridDim.x) {
        const int row0 = tile * 128;

        // ---- Stage A chunk 0 (x columns 0..31) ----
        #pragma unroll
        for (int i = 0; i < 2; i++) {
            int g  = tid + i * 256;
            int r  = g >> 2;
            int k8 = g & 3;
            int gr = row0 + r;
            float4 lo = make_float4(0.f, 0.f, 0.f, 0.f);
            float4 hi = lo;
            if (gr < N) {
                const float4* src = reinterpret_cast<const float4*>(x);
                lo = src[(size_t)gr * 32 + k8 * 2];
                hi = src[(size_t)gr * 32 + k8 * 2 + 1];
            }
            float* dst = sA0 + r * STRIDE_A + k8 * 8;
            reinterpret_cast<float4*>(dst)[0] =
                make_float4(to_tf32(lo.x), to_tf32(hi.x), to_tf32(lo.y), to_tf32(hi.y));
            reinterpret_cast<float4*>(dst)[1] =
                make_float4(to_tf32(lo.z), to_tf32(hi.z), to_tf32(lo.w), to_tf32(hi.w));
        }
        __syncthreads();   // also fences previous tile's last-chunk readers

        float d[2][8][4];
        #pragma unroll
        for (int m = 0; m < 2; m++)
            #pragma unroll
            for (int j = 0; j < 8; j++)
                #pragma unroll
                for (int q = 0; q < 4; q++)
                    d[m][j][q] = 0.f;

        for (int c = 0; c < 8; c++) {
            // Prefetch chunk c+1 into registers (global loads only)
            float4 plo[2], phi[2];
            if (c < 7) {
                int cn = c + 1;
                const float4* src = reinterpret_cast<const float4*>(cn < 4 ? x : g_agg);
                #pragma unroll
                for (int i = 0; i < 2; i++) {
                    int g  = tid + i * 256;
                    int r  = g >> 2;
                    int k8 = g & 3;
                    int gr = row0 + r;
                    plo[i] = make_float4(0.f, 0.f, 0.f, 0.f);
                    phi[i] = plo[i];
                    if (gr < N) {
                        size_t base = (size_t)gr * 32 + (cn & 3) * 8 + k8 * 2;
                        plo[i] = src[base];
                        phi[i] = src[base + 1];
                    }
                }
            }

            const float* bufA = bufs[c & 1];
            const int kglob0 = c * 32;
            #pragma unroll
            for (int kk = 0; kk < 4; kk++) {
                int k0 = kk * 8;
                unsigned a[2][4];
                #pragma unroll
                for (int m = 0; m < 2; m++) {
                    int row = warp_m * 32 + m * 16 + gid;
                    float2 v0 = reinterpret_cast<const float2*>(bufA + row * STRIDE_A + k0)[tig];
                    float2 v1 = reinterpret_cast<const float2*>(bufA + (row + 8) * STRIDE_A + k0)[tig];
                    a[m][0] = __float_as_uint(v0.x);
                    a[m][1] = __float_as_uint(v1.x);
                    a[m][2] = __float_as_uint(v0.y);
                    a[m][3] = __float_as_uint(v1.y);
                }
                unsigned b0[8], b1[8];
                #pragma unroll
                for (int j = 0; j < 8; j++) {
                    int n = warp_n * 64 + j * 8 + gid;
                    float2 w = reinterpret_cast<const float2*>(sW + n * STRIDE_W + kglob0 + k0)[tig];
                    b0[j] = __float_as_uint(w.x);
                    b1[j] = __float_as_uint(w.y);
                }
                #pragma unroll
                for (int m = 0; m < 2; m++)
                    #pragma unroll
                    for (int j = 0; j < 8; j++)
                        mma_tf32(d[m][j], a[m], b0[j], b1[j]);
            }

            if (c < 7) {
                __syncthreads();
                float* dstB = bufs[(c + 1) & 1];
                #pragma unroll
                for (int i = 0; i < 2; i++) {
                    int g  = tid + i * 256;
                    int r  = g >> 2;
                    int k8 = g & 3;
                    float* dst = dstB + r * STRIDE_A + k8 * 8;
                    reinterpret_cast<float4*>(dst)[0] =
                        make_float4(to_tf32(plo[i].x), to_tf32(phi[i].x),
                                    to_tf32(plo[i].y), to_tf32(phi[i].y));
                    reinterpret_cast<float4*>(dst)[1] =
                        make_float4(to_tf32(plo[i].z), to_tf32(phi[i].z),
                                    to_tf32(plo[i].w), to_tf32(phi[i].w));
                }
                __syncthreads();
            }
        }

        // ---- Epilogue: relu + float2 stores ----
        #pragma unroll
        for (int m = 0; m < 2; m++) {
            int r = row0 + warp_m * 32 + m * 16 + gid;
            #pragma unroll
            for (int j = 0; j < 8; j++) {
                int cbase = warp_n * 64 + j * 8 + tig * 2;
                if (r < N) {
                    float2 o = make_float2(fmaxf(d[m][j][0], 0.f), fmaxf(d[m][j][1], 0.f));
                    *reinterpret_cast<float2*>(out + (size_t)r * 128 + cbase) = o;
                }
                if (r + 8 < N) {
                    float2 o = make_float2(fmaxf(d[m][j][2], 0.f), fmaxf(d[m][j][3], 0.f));
                    *reinterpret_cast<float2*>(out + (size_t)(r + 8) * 128 + cbase) = o;
                }
            }
        }
        __syncthreads();   // protect sA0 restage on next tile iteration
    }
}

// ---------------------------------------------------------------------------
// Launch
// ---------------------------------------------------------------------------
extern "C" void kernel_launch(void* const* d_in, const int* in_sizes, int n_in,
                              void* d_out, int out_size) {
    const float* x  = (const float*)d_in[0];
    const int*   ei = (const int*)d_in[1];
    const float* W1 = (const float*)d_in[2];
    const float* W2 = (const float*)d_in[3];
    float* out = (float*)d_out;

    int N = in_sizes[0] / DIMS;       // 100000
    int E = in_sizes[1] / 2;          // 1600000
    int NB = (N + 511) / 512;         // 196 scan blocks

    // CSR build
    k_clear_deg<<<(N + 255) / 256, 256>>>(N);
    k_hist<<<(E + 255) / 256, 256>>>(ei, E, N);
    k_scan_block<<<NB, 512>>>(N);
    k_scan_top<<<1, 256>>>(NB);
    k_scan_add<<<(N + 255) / 256, 256>>>(N);
    k_fill<<<(E + 255) / 256, 256>>>(ei, E, N);

    // Gather-aggregate (writes g_agg fully; no zero pass)
    {
        size_t threads = (size_t)N * 32;
        int blocks = (int)((threads + 255) / 256);
        k_aggregate<<<blocks, 256>>>(x, N);
    }

    // Persistent tf32 tensor-core GEMM + relu
    {
        int smem_bytes = (SMEM_W_FLOATS + 2 * SMEM_A_FLOATS) * sizeof(float); // 176128
        cudaFuncSetAttribute(k_mma_gemm,
                             cudaFuncAttributeMaxDynamicSharedMemorySize,
                             smem_bytes);
        k_mma_gemm<<<148, 256, smem_bytes>>>(x, W1, W2, out, N);
    }
}